// round 1
// baseline (speedup 1.0000x reference)
#include <cuda_runtime.h>
#include <cstdint>

#define N_GROUPS 262144
#define EMBED_DIM 64

// 8 lanes per group, 4 groups per warp.
// Each lane covers dims {4*lsub+k, 32+4*lsub+k} for k=0..3 via two float4 loads
// per embedding row (fully coalesced 256B row fetch across the 8 lanes).
__global__ __launch_bounds__(256, 2)
void afm_kernel(const int*   __restrict__ group,
                const float* __restrict__ embed,
                const float* __restrict__ W1,
                const float* __restrict__ b1,
                const float* __restrict__ W2,
                const float* __restrict__ b2,
                const float* __restrict__ Wp,
                const float* __restrict__ bp,
                float*       __restrict__ out)
{
    const int lane = threadIdx.x & 31;
    const int sub  = lane >> 3;   // which of 4 groups in this warp
    const int lsub = lane & 7;    // lane within the 8-lane subgroup

    const int warp_global = (blockIdx.x * blockDim.x + threadIdx.x) >> 5;
    const int nwarps      = (gridDim.x * blockDim.x) >> 5;

    // Per-lane W1 slice: rows (4*lsub+k) and (32+4*lsub+k), each row = 4 floats.
    float4 w1r[8];
#pragma unroll
    for (int h = 0; h < 2; h++)
#pragma unroll
        for (int k = 0; k < 4; k++)
            w1r[h * 4 + k] =
                *reinterpret_cast<const float4*>(W1 + (h * 32 + lsub * 4 + k) * 4);

    const float b10 = b1[0], b11 = b1[1], b12 = b1[2], b13 = b1[3];
    const float w20 = W2[0], w21 = W2[1], w22 = W2[2], w23 = W2[3];
    const float b2r = b2[0];
    const float wp0 = Wp[0], wp1 = Wp[1], wp2 = Wp[2];
    const float bpr = bp[0];

    for (int g0 = warp_global * 4; g0 < N_GROUPS; g0 += nwarps * 4) {
        // Cooperative index load: 12 indices for the warp's 4 groups.
        int v = 0;
        if (lane < 12) v = group[g0 * 3 + lane];
        const int i0 = __shfl_sync(0xffffffffu, v, sub * 3 + 0);
        const int i1 = __shfl_sync(0xffffffffu, v, sub * 3 + 1);
        const int i2 = __shfl_sync(0xffffffffu, v, sub * 3 + 2);

        const float4* r0 = reinterpret_cast<const float4*>(embed + (size_t)i0 * EMBED_DIM);
        const float4* r1 = reinterpret_cast<const float4*>(embed + (size_t)i1 * EMBED_DIM);
        const float4* r2 = reinterpret_cast<const float4*>(embed + (size_t)i2 * EMBED_DIM);

        const float4 e0a = r0[lsub], e0b = r0[lsub + 8];
        const float4 e1a = r1[lsub], e1b = r1[lsub + 8];
        const float4 e2a = r2[lsub], e2b = r2[lsub + 8];

        float acc00 = 0.f, acc01 = 0.f, acc02 = 0.f, acc03 = 0.f;  // pair (0,1)
        float acc10 = 0.f, acc11 = 0.f, acc12 = 0.f, acc13 = 0.f;  // pair (0,2)
        float acc20 = 0.f, acc21 = 0.f, acc22 = 0.f, acc23 = 0.f;  // pair (1,2)

#define DIM(x0, x1, x2, W)                                   \
        {                                                    \
            const float v01 = (x0) * (x1);                   \
            const float v02 = (x0) * (x2);                   \
            const float v12 = (x1) * (x2);                   \
            acc00 = fmaf(v01, (W).x, acc00);                 \
            acc01 = fmaf(v01, (W).y, acc01);                 \
            acc02 = fmaf(v01, (W).z, acc02);                 \
            acc03 = fmaf(v01, (W).w, acc03);                 \
            acc10 = fmaf(v02, (W).x, acc10);                 \
            acc11 = fmaf(v02, (W).y, acc11);                 \
            acc12 = fmaf(v02, (W).z, acc12);                 \
            acc13 = fmaf(v02, (W).w, acc13);                 \
            acc20 = fmaf(v12, (W).x, acc20);                 \
            acc21 = fmaf(v12, (W).y, acc21);                 \
            acc22 = fmaf(v12, (W).z, acc22);                 \
            acc23 = fmaf(v12, (W).w, acc23);                 \
        }

        DIM(e0a.x, e1a.x, e2a.x, w1r[0]);
        DIM(e0a.y, e1a.y, e2a.y, w1r[1]);
        DIM(e0a.z, e1a.z, e2a.z, w1r[2]);
        DIM(e0a.w, e1a.w, e2a.w, w1r[3]);
        DIM(e0b.x, e1b.x, e2b.x, w1r[4]);
        DIM(e0b.y, e1b.y, e2b.y, w1r[5]);
        DIM(e0b.z, e1b.z, e2b.z, w1r[6]);
        DIM(e0b.w, e1b.w, e2b.w, w1r[7]);
#undef DIM

        // Butterfly reduction within the 8-lane subgroup (xor 1,2,4 stays
        // inside aligned 8-lane chunks).
#define RED(a)                                               \
        a += __shfl_xor_sync(0xffffffffu, a, 1);             \
        a += __shfl_xor_sync(0xffffffffu, a, 2);             \
        a += __shfl_xor_sync(0xffffffffu, a, 4);
        RED(acc00) RED(acc01) RED(acc02) RED(acc03)
        RED(acc10) RED(acc11) RED(acc12) RED(acc13)
        RED(acc20) RED(acc21) RED(acc22) RED(acc23)
#undef RED

        if (lsub == 0) {
            // attention MLP epilogue for this group
            auto sig = [](float x) {
                return __fdividef(1.0f, 1.0f + __expf(-x));
            };
            float a0 = b2r, a1 = b2r, a2 = b2r;
            a0 += sig(acc00 + b10) * w20;
            a0 += sig(acc01 + b11) * w21;
            a0 += sig(acc02 + b12) * w22;
            a0 += sig(acc03 + b13) * w23;

            a1 += sig(acc10 + b10) * w20;
            a1 += sig(acc11 + b11) * w21;
            a1 += sig(acc12 + b12) * w22;
            a1 += sig(acc13 + b13) * w23;

            a2 += sig(acc20 + b10) * w20;
            a2 += sig(acc21 + b11) * w21;
            a2 += sig(acc22 + b12) * w22;
            a2 += sig(acc23 + b13) * w23;

            const float o = bpr + a0 * wp0 + a1 * wp1 + a2 * wp2;
            out[g0 + sub] = sig(o) * 2.0f - 1.0f;
        }
    }
}

extern "C" void kernel_launch(void* const* d_in, const int* in_sizes, int n_in,
                              void* d_out, int out_size)
{
    const int*   group = (const int*)  d_in[0];
    const float* embed = (const float*)d_in[1];
    const float* W1    = (const float*)d_in[2];
    const float* b1    = (const float*)d_in[3];
    const float* W2    = (const float*)d_in[4];
    const float* b2    = (const float*)d_in[5];
    const float* Wp    = (const float*)d_in[6];
    const float* bp    = (const float*)d_in[7];
    float* out = (float*)d_out;

    // 148 SMs * 8 blocks: grid-stride amortizes the per-thread W1 register load.
    const int blocks  = 1184;
    const int threads = 256;
    afm_kernel<<<blocks, threads>>>(group, embed, W1, b1, W2, b2, Wp, bp, out);
}